// round 16
// baseline (speedup 1.0000x reference)
#include <cuda_runtime.h>
#include <cuda_fp16.h>
#include <cstdint>
#include <math.h>

#define Hh   4
#define Cc   64
#define HC   256
#define INC  256
#define HIDD 64
#define OUTC 40
#define NEG  0.2f

#define N_MAX  50048
#define E_MAX  800000
#define ET_MAX (E_MAX + N_MAX)

// ---------------- static scratch (zero-initialized at load; self-resetting) ----------------
__device__ __align__(16) __half g_hh[(size_t)N_MAX * HC];    // h in fp16
__device__ __align__(16) __half g_agg[(size_t)N_MAX * HC];   // relu(agg/den+bias), fp16
__device__ float g_asrc[N_MAX * Hh];
__device__ float g_adst[N_MAX * Hh];
__device__ int   g_deg[N_MAX];
__device__ int   g_cnt[N_MAX];
__device__ int   g_off[N_MAX];
__device__ int   g_cursor;
__device__ int   g_csr_src[ET_MAX];

// fp16 operands for tensor-core GEMMs
__device__ __align__(16) __half g_xhi[(size_t)N_MAX * 256];
__device__ __align__(16) __half g_bhi[256 * 256];            // B[n,k] = W[k,n]
__device__ __align__(16) __half g_w1hi[64 * 256];            // W1[k,n] -> [n,k] hi
__device__ __align__(16) __half g_w1lo[64 * 256];            // lo

__device__ __forceinline__ int clampi(int v, int n) {
    return (v < 0) ? 0 : ((v >= n) ? n - 1 : v);
}

// ---------------- packed fp32x2 helpers ----------------
__device__ __forceinline__ unsigned long long pk2(float lo, float hi) {
    unsigned long long r;
    asm("mov.b64 %0, {%1, %2};" : "=l"(r) : "f"(lo), "f"(hi));
    return r;
}
__device__ __forceinline__ float2 upk2(unsigned long long v) {
    float lo, hi;
    asm("mov.b64 {%0, %1}, %2;" : "=f"(lo), "=f"(hi) : "l"(v));
    return make_float2(lo, hi);
}
__device__ __forceinline__ unsigned long long ffma2(unsigned long long a,
                                                    unsigned long long b,
                                                    unsigned long long c) {
    unsigned long long d;
    asm("fma.rn.f32x2 %0, %1, %2, %3;" : "=l"(d) : "l"(a), "l"(b), "l"(c));
    return d;
}

// ---------------- warp-level fp16 MMA + ldmatrix ----------------
__device__ __forceinline__ void mma_f16(float* d, const uint32_t* a, const uint32_t* b) {
    asm volatile(
        "mma.sync.aligned.m16n8k16.row.col.f32.f16.f16.f32 "
        "{%0,%1,%2,%3}, {%4,%5,%6,%7}, {%8,%9}, {%0,%1,%2,%3};"
        : "+f"(d[0]), "+f"(d[1]), "+f"(d[2]), "+f"(d[3])
        : "r"(a[0]), "r"(a[1]), "r"(a[2]), "r"(a[3]), "r"(b[0]), "r"(b[1]));
}
__device__ __forceinline__ void ldsm_x4(uint32_t* r, uint32_t addr) {
    asm volatile("ldmatrix.sync.aligned.m8n8.x4.shared.b16 {%0,%1,%2,%3}, [%4];"
                 : "=r"(r[0]), "=r"(r[1]), "=r"(r[2]), "=r"(r[3]) : "r"(addr));
}

// ---------------- cp.async helpers ----------------
__device__ __forceinline__ uint32_t smem_u32(const void* p) {
    uint32_t a;
    asm("{ .reg .u64 t; cvta.to.shared.u64 t, %1; cvt.u32.u64 %0, t; }" : "=r"(a) : "l"(p));
    return a;
}
__device__ __forceinline__ void cpa16(uint32_t dst, const void* src, bool pred) {
    int sz = pred ? 16 : 0;
    asm volatile("cp.async.cg.shared.global [%0], [%1], 16, %2;"
                 :: "r"(dst), "l"(src), "r"(sz));
}
#define CPA_COMMIT() asm volatile("cp.async.commit_group;" ::: "memory")
#define CPA_WAIT(n)  asm volatile("cp.async.wait_group %0;" :: "n"(n) : "memory")

// ---------------- fused: fp32->fp16 x  +  edge in-degree count ----------------
__global__ void convx_deg_kernel(const float* __restrict__ x,
                                 const int* __restrict__ ei,
                                 int Nn, int E, int ET) {
    int i = blockIdx.x * blockDim.x + threadIdx.x;
    int tot = Nn * 64;
    if (i < tot) {
        float4 v = ((const float4*)x)[i];
        __half2* ph = (__half2*)g_xhi;
        ph[i * 2 + 0] = __floats2half2_rn(v.x, v.y);
        ph[i * 2 + 1] = __floats2half2_rn(v.z, v.w);
    }
    if (i < ET) {
        int d = (i < E) ? clampi(ei[(size_t)E + i], Nn) : (i - E);
        atomicAdd(&g_deg[d], 1);
    }
}

// ---------------- fused: W -> bhi, W1 -> w1hi/lo, CSR offsets ----------------
__global__ void convw_off_kernel(const float* __restrict__ W,
                                 const float* __restrict__ W1, int Nn) {
    int idx = blockIdx.x * blockDim.x + threadIdx.x;
    if (idx < 256 * 256) {
        int n = idx & 255, k = idx >> 8;
        g_bhi[n * 256 + k] = __float2half_rn(W[k * 256 + n]);
    }
    if (idx < 64 * 256) {
        int n = idx & 63, k = idx >> 6;
        float w = W1[k * 64 + n];
        __half h = __float2half_rn(w);
        __half l = __float2half_rn(w - __half2float(h));
        g_w1hi[n * 256 + k] = h;
        g_w1lo[n * 256 + k] = l;
    }
    if (idx < Nn)
        g_off[idx] = atomicAdd(&g_cursor, g_deg[idx]);
}

// ---------------- CSR fill: slot assignment only (no logits needed) ----------------
__global__ void csr_fill_kernel(const int* __restrict__ ei, int E, int ET, int Nn) {
    int e = blockIdx.x * blockDim.x + threadIdx.x;
    if (e >= ET) return;
    int s, d;
    if (e < E) { s = clampi(ei[e], Nn); d = clampi(ei[(size_t)E + e], Nn); }
    else       { s = d = e - E; }
    int slot = g_off[d] + atomicAdd(&g_cnt[d], 1);
    g_csr_src[slot] = s;
}

// ---------------- tensor GEMM (1-term fp16) + fused attention epilogue ----------------
// 256 threads, 8 warps 4m x 2n (warp tile 32x64), 2 CTAs/SM for overlap.
#define APAD    72
#define TILE_EL (128 * APAD)
#define STAGE_EL (2 * TILE_EL)
#define GEMM_SMEM_BYTES (2 * STAGE_EL * 2)   // 73728

__global__ void __launch_bounds__(256, 2)
gemm_mma_kernel(const float* __restrict__ att_src,
                const float* __restrict__ att_dst, int Nn) {
    extern __shared__ __half sm[];
    int tid  = threadIdx.x;
    int wid  = tid >> 5;
    int lane = tid & 31;
    int gid  = lane >> 2;
    int tig  = lane & 3;
    int wm   = (wid & 3) * 32;
    int wn   = (wid >> 2) * 64;
    int m0 = blockIdx.x * 128;
    int n0 = blockIdx.y * 128;

    float acc[2][8][4];
#pragma unroll
    for (int mt = 0; mt < 2; mt++)
#pragma unroll
        for (int nt = 0; nt < 8; nt++)
#pragma unroll
            for (int q = 0; q < 4; q++) acc[mt][nt][q] = 0.f;

    uint32_t aoff = (uint32_t)((wm + ((lane >> 3) & 1) * 8 + (lane & 7)) * APAD
                               + (lane >> 4) * 8) * 2;
    uint32_t boff = (uint32_t)((wn + (lane >> 4) * 8 + (lane & 7)) * APAD
                               + ((lane >> 3) & 1) * 8) * 2;

    auto stage_load = [&](int st, int kk) {
        __half* base = sm + st * STAGE_EL;
        uint32_t sA = smem_u32(base);
        uint32_t sB = sA + TILE_EL * 2;
#pragma unroll
        for (int j0 = 0; j0 < 1024; j0 += 256) {
            int j = j0 + tid;
            int r = j >> 3, u = (j & 7) * 8;
            uint32_t so = (uint32_t)(r * APAD + u) * 2;
            bool am = (m0 + r) < Nn;
            size_t ga = (size_t)(m0 + r) * 256 + kk + u;
            size_t gb = (size_t)(n0 + r) * 256 + kk + u;
            cpa16(sA + so, g_xhi + ga, am);
            cpa16(sB + so, g_bhi + gb, true);
        }
        CPA_COMMIT();
    };

    stage_load(0, 0);

    for (int c = 0; c < 4; c++) {
        if (c < 3) stage_load((c + 1) & 1, (c + 1) * 64);
        if (c < 3) { CPA_WAIT(1); } else { CPA_WAIT(0); }
        __syncthreads();

        uint32_t base = smem_u32(sm + (c & 1) * STAGE_EL);
        uint32_t aHi = base + aoff;
        uint32_t bHi = base + TILE_EL * 2 + boff;

#pragma unroll
        for (int ks = 0; ks < 64; ks += 16) {
            uint32_t ahi[2][4], bhi[4][4];
#pragma unroll
            for (int mt = 0; mt < 2; mt++) {
                uint32_t d = (uint32_t)(mt * 16 * APAD + ks) * 2;
                ldsm_x4(ahi[mt], aHi + d);
            }
#pragma unroll
            for (int p = 0; p < 4; p++) {
                uint32_t d = (uint32_t)(p * 16 * APAD + ks) * 2;
                ldsm_x4(bhi[p], bHi + d);
            }
#pragma unroll
            for (int mt = 0; mt < 2; mt++)
#pragma unroll
                for (int nt = 0; nt < 8; nt++)
                    mma_f16(acc[mt][nt], ahi[mt], &bhi[nt >> 1][(nt & 1) * 2]);
        }
        __syncthreads();
    }

    // ---- epilogue 1: store h as fp16 ----
#pragma unroll
    for (int mt = 0; mt < 2; mt++) {
        int row = m0 + wm + mt * 16 + gid;
#pragma unroll
        for (int nt = 0; nt < 8; nt++) {
            int col = n0 + wn + nt * 8 + tig * 2;
            if (row < Nn)
                *(__half2*)(g_hh + (size_t)row * 256 + col) =
                    __floats2half2_rn(acc[mt][nt][0], acc[mt][nt][1]);
            if (row + 8 < Nn)
                *(__half2*)(g_hh + (size_t)(row + 8) * 256 + col) =
                    __floats2half2_rn(acc[mt][nt][2], acc[mt][nt][3]);
        }
    }

    // ---- epilogue 2: fused attention logits ----
    float* sA = (float*)sm;          // [128][2]
    float* sD = sA + 256;            // [128][2]
    if (tid < 256) { sA[tid] = 0.f; sD[tid] = 0.f; }
    __syncthreads();

    int lh = wn >> 6;                // local head 0/1 (warp-uniform)
    const float* ats = att_src + (blockIdx.y * 2 + lh) * 64;
    const float* atd = att_dst + (blockIdx.y * 2 + lh) * 64;

#pragma unroll
    for (int mt = 0; mt < 2; mt++) {
        float s0 = 0.f, d0 = 0.f, s1 = 0.f, d1 = 0.f;
#pragma unroll
        for (int nt = 0; nt < 8; nt++)
#pragma unroll
            for (int q = 0; q < 2; q++) {
                int cc = nt * 8 + tig * 2 + q;   // 0..63 within head
                float ws = __ldg(ats + cc);
                float wd = __ldg(atd + cc);
                s0 = fmaf(acc[mt][nt][q], ws, s0);
                d0 = fmaf(acc[mt][nt][q], wd, d0);
                s1 = fmaf(acc[mt][nt][q + 2], ws, s1);
                d1 = fmaf(acc[mt][nt][q + 2], wd, d1);
            }
#pragma unroll
        for (int off = 1; off <= 2; off <<= 1) {
            s0 += __shfl_xor_sync(0xffffffffu, s0, off);
            d0 += __shfl_xor_sync(0xffffffffu, d0, off);
            s1 += __shfl_xor_sync(0xffffffffu, s1, off);
            d1 += __shfl_xor_sync(0xffffffffu, d1, off);
        }
        if (tig == 0) {
            int r0 = wm + mt * 16 + gid;
            atomicAdd(&sA[r0 * 2 + lh], s0);
            atomicAdd(&sD[r0 * 2 + lh], d0);
            atomicAdd(&sA[(r0 + 8) * 2 + lh], s1);
            atomicAdd(&sD[(r0 + 8) * 2 + lh], d1);
        }
    }
    __syncthreads();
    if (tid < 256) {
        int r = tid >> 1, h2 = tid & 1;
        int grow = m0 + r;
        if (grow < Nn) {
            int gh = blockIdx.y * 2 + h2;
            g_asrc[grow * 4 + gh] = sA[r * 2 + h2];
            g_adst[grow * 4 + gh] = sD[r * 2 + h2];
        }
    }
}

// ---------------- aggregation: 32 threads/node, inline softmax + fp16 gather ----------------
// Computes a = exp(leaky(asrc[src] + adst[node])) inline (fp32 — better precision),
// then resets the per-node counters for the next graph replay.
__global__ void agg_kernel(const float* __restrict__ bias_conv, int Nn) {
    int node = blockIdx.x * 8 + (threadIdx.x >> 5);
    int l    = threadIdx.x & 31;
    if (node >= Nn) return;
    int beg = g_off[node];
    int deg = g_deg[node];
    int hd  = l >> 3;
    float adst_n = g_adst[node * 4 + hd];

    float acc[8];
#pragma unroll
    for (int q = 0; q < 8; q++) acc[q] = 0.f;
    float den = 0.f;
#pragma unroll 2
    for (int i = 0; i < deg; i++) {
        int slot = beg + i;
        int s    = g_csr_src[slot];
        float lv = g_asrc[s * 4 + hd] + adst_n;
        lv = (lv > 0.f) ? lv : NEG * lv;
        float a  = __expf(lv);
        uint4 hv = *(const uint4*)(g_hh + (size_t)s * 256 + l * 8);
        __half2 p0 = *(__half2*)&hv.x, p1 = *(__half2*)&hv.y;
        __half2 p2 = *(__half2*)&hv.z, p3 = *(__half2*)&hv.w;
        float2 f0 = __half22float2(p0), f1 = __half22float2(p1);
        float2 f2 = __half22float2(p2), f3 = __half22float2(p3);
        den += a;
        acc[0] = fmaf(a, f0.x, acc[0]); acc[1] = fmaf(a, f0.y, acc[1]);
        acc[2] = fmaf(a, f1.x, acc[2]); acc[3] = fmaf(a, f1.y, acc[3]);
        acc[4] = fmaf(a, f2.x, acc[4]); acc[5] = fmaf(a, f2.y, acc[5]);
        acc[6] = fmaf(a, f3.x, acc[6]); acc[7] = fmaf(a, f3.y, acc[7]);
    }
    float r = 1.f / den;
    float4 b0 = *(const float4*)(bias_conv + l * 8);
    float4 b1 = *(const float4*)(bias_conv + l * 8 + 4);
    float o[8];
    o[0] = fmaxf(fmaf(acc[0], r, b0.x), 0.f);
    o[1] = fmaxf(fmaf(acc[1], r, b0.y), 0.f);
    o[2] = fmaxf(fmaf(acc[2], r, b0.z), 0.f);
    o[3] = fmaxf(fmaf(acc[3], r, b0.w), 0.f);
    o[4] = fmaxf(fmaf(acc[4], r, b1.x), 0.f);
    o[5] = fmaxf(fmaf(acc[5], r, b1.y), 0.f);
    o[6] = fmaxf(fmaf(acc[6], r, b1.z), 0.f);
    o[7] = fmaxf(fmaf(acc[7], r, b1.w), 0.f);
    uint4 ov;
    ((__half2*)&ov)[0] = __floats2half2_rn(o[0], o[1]);
    ((__half2*)&ov)[1] = __floats2half2_rn(o[2], o[3]);
    ((__half2*)&ov)[2] = __floats2half2_rn(o[4], o[5]);
    ((__half2*)&ov)[3] = __floats2half2_rn(o[6], o[7]);
    *(uint4*)(g_agg + (size_t)node * HC + l * 8) = ov;

    // self-reset for next replay (each node visited exactly once)
    if (l == 0) {
        g_deg[node] = 0;
        g_cnt[node] = 0;
        if (node == 0) g_cursor = 0;
    }
}

// ---------------- fused MLP via tensor cores (2 CTAs/SM) ----------------
#define MTILE_A   (128 * APAD)
#define MTILE_B   (64 * APAD)
#define MSTAGE_EL (MTILE_A + 2 * MTILE_B)
#define MLP_SMEM_BYTES (2 * MSTAGE_EL * 2)   // 73728

__global__ void __launch_bounds__(256, 2)
mlp_mma_kernel(const float* __restrict__ b1,
               const float* __restrict__ W2, const float* __restrict__ b2,
               float* __restrict__ out, int M) {
    extern __shared__ __half sm[];
    int tid  = threadIdx.x;
    int wid  = tid >> 5;
    int lane = tid & 31;
    int gid  = lane >> 2;
    int tig  = lane & 3;
    int wm   = (wid & 3) * 32;
    int wn   = (wid >> 2) * 32;
    int m0 = blockIdx.x * 128;

    float acc[2][4][4];
#pragma unroll
    for (int mt = 0; mt < 2; mt++)
#pragma unroll
        for (int nt = 0; nt < 4; nt++)
#pragma unroll
            for (int q = 0; q < 4; q++) acc[mt][nt][q] = 0.f;

    uint32_t aoff = (uint32_t)((wm + ((lane >> 3) & 1) * 8 + (lane & 7)) * APAD
                               + (lane >> 4) * 8) * 2;
    uint32_t boff = (uint32_t)((wn + (lane >> 4) * 8 + (lane & 7)) * APAD
                               + ((lane >> 3) & 1) * 8) * 2;

    auto stage_load = [&](int st, int kk) {
        __half* base = sm + st * MSTAGE_EL;
        uint32_t sA  = smem_u32(base);
        uint32_t sBh = sA + MTILE_A * 2;
        uint32_t sBl = sBh + MTILE_B * 2;
#pragma unroll
        for (int j0 = 0; j0 < 1024; j0 += 256) {
            int j = j0 + tid;
            int r = j >> 3, u = (j & 7) * 8;
            uint32_t so = (uint32_t)(r * APAD + u) * 2;
            bool am = (m0 + r) < M;
            cpa16(sA + so, g_agg + (size_t)(m0 + r) * 256 + kk + u, am);
        }
#pragma unroll
        for (int j0 = 0; j0 < 512; j0 += 256) {
            int j = j0 + tid;
            int r = j >> 3, u = (j & 7) * 8;
            uint32_t so = (uint32_t)(r * APAD + u) * 2;
            cpa16(sBh + so, g_w1hi + (size_t)r * 256 + kk + u, true);
            cpa16(sBl + so, g_w1lo + (size_t)r * 256 + kk + u, true);
        }
        CPA_COMMIT();
    };

    stage_load(0, 0);

    for (int c = 0; c < 4; c++) {
        if (c < 3) stage_load((c + 1) & 1, (c + 1) * 64);
        if (c < 3) { CPA_WAIT(1); } else { CPA_WAIT(0); }
        __syncthreads();

        uint32_t base = smem_u32(sm + (c & 1) * MSTAGE_EL);
        uint32_t aA  = base + aoff;
        uint32_t bHi = base + MTILE_A * 2 + boff;
        uint32_t bLo = bHi + MTILE_B * 2;

#pragma unroll
        for (int ks = 0; ks < 64; ks += 16) {
            uint32_t av[2][4], bh[2][4], bl[2][4];
#pragma unroll
            for (int mt = 0; mt < 2; mt++) {
                uint32_t d = (uint32_t)(mt * 16 * APAD + ks) * 2;
                ldsm_x4(av[mt], aA + d);
            }
#pragma unroll
            for (int p = 0; p < 2; p++) {
                uint32_t d = (uint32_t)(p * 16 * APAD + ks) * 2;
                ldsm_x4(bh[p], bHi + d);
                ldsm_x4(bl[p], bLo + d);
            }
#pragma unroll
            for (int mt = 0; mt < 2; mt++)
#pragma unroll
                for (int nt = 0; nt < 4; nt++)
                    mma_f16(acc[mt][nt], av[mt], &bh[nt >> 1][(nt & 1) * 2]);
#pragma unroll
            for (int mt = 0; mt < 2; mt++)
#pragma unroll
                for (int nt = 0; nt < 4; nt++)
                    mma_f16(acc[mt][nt], av[mt], &bl[nt >> 1][(nt & 1) * 2]);
        }
        __syncthreads();
    }

    // ---- epilogue: bias+relu -> sHid (smem fp16), then per-thread mlp2 ----
    __half* sHid = sm;                          // [128][66]
    float*  sW2  = (float*)(sm + 8448);         // [64][40]
    float*  sb2  = sW2 + 2560;                  // [40]

    for (int i = tid; i < 2560; i += 256) sW2[i] = W2[i];
    if (tid < 40) sb2[tid] = b2[tid];

#pragma unroll
    for (int mt = 0; mt < 2; mt++) {
        int rl = wm + mt * 16 + gid;
#pragma unroll
        for (int nt = 0; nt < 4; nt++) {
            int col = wn + nt * 8 + tig * 2;
            float bc0 = __ldg(b1 + col), bc1 = __ldg(b1 + col + 1);
            *(__half2*)(sHid + rl * 66 + col) =
                __floats2half2_rn(fmaxf(acc[mt][nt][0] + bc0, 0.f),
                                  fmaxf(acc[mt][nt][1] + bc1, 0.f));
            *(__half2*)(sHid + (rl + 8) * 66 + col) =
                __floats2half2_rn(fmaxf(acc[mt][nt][2] + bc0, 0.f),
                                  fmaxf(acc[mt][nt][3] + bc1, 0.f));
        }
    }
    __syncthreads();

    int row  = tid & 127;
    int half_ = tid >> 7;          // 0/1: which 20 output cols
    int node = m0 + row;
    if (node >= M) return;

    unsigned long long acc2[10];
#pragma unroll
    for (int j = 0; j < 10; j++) {
        float2 bv = *(const float2*)(sb2 + half_ * 20 + j * 2);
        acc2[j] = pk2(bv.x, bv.y);
    }
#pragma unroll 4
    for (int k = 0; k < HIDD; k++) {
        float xv = __half2float(sHid[row * 66 + k]);
        unsigned long long xp = pk2(xv, xv);
        const float2* wrow = (const float2*)(sW2 + k * OUTC + half_ * 20);
#pragma unroll
        for (int j = 0; j < 10; j++) {
            float2 w = wrow[j];
            acc2[j] = ffma2(xp, pk2(w.x, w.y), acc2[j]);
        }
    }
    float* orow = out + (size_t)node * OUTC + half_ * 20;
#pragma unroll
    for (int j = 0; j < 10; j++) {
        float2 v = upk2(acc2[j]);
        *(float2*)(orow + j * 2) = v;
    }
}

// ---------------- launch ----------------
extern "C" void kernel_launch(void* const* d_in, const int* in_sizes, int n_in,
                              void* d_out, int out_size) {
    const float* x         = (const float*)d_in[0];
    const int*   ei        = (const int*)d_in[1];      // int32
    const float* W         = (const float*)d_in[2];
    const float* att_src   = (const float*)d_in[3];
    const float* att_dst   = (const float*)d_in[4];
    const float* bias_conv = (const float*)d_in[5];
    const float* W1        = (const float*)d_in[6];
    const float* b1        = (const float*)d_in[7];
    const float* W2        = (const float*)d_in[8];
    const float* b2        = (const float*)d_in[9];
    float*       out       = (float*)d_out;

    int Nn = in_sizes[0] / INC;
    int E  = in_sizes[1] / 2;
    int ET = E + Nn;

    cudaFuncSetAttribute(gemm_mma_kernel,
                         cudaFuncAttributeMaxDynamicSharedMemorySize, GEMM_SMEM_BYTES);
    cudaFuncSetAttribute(mlp_mma_kernel,
                         cudaFuncAttributeMaxDynamicSharedMemorySize, MLP_SMEM_BYTES);

    int t1 = Nn * 64; if (ET > t1) t1 = ET;
    convx_deg_kernel<<<(t1 + 255) / 256, 256>>>(x, ei, Nn, E, ET);
    convw_off_kernel<<<(256 * 256 + 255) / 256, 256>>>(W, W1, Nn);
    csr_fill_kernel<<<(ET + 255) / 256, 256>>>(ei, E, ET, Nn);

    dim3 gt((Nn + 127) / 128, 2);
    gemm_mma_kernel<<<gt, 256, GEMM_SMEM_BYTES>>>(att_src, att_dst, Nn);

    agg_kernel<<<(Nn + 7) / 8, 256>>>(bias_conv, Nn);

    mlp_mma_kernel<<<(Nn + 127) / 128, 256, MLP_SMEM_BYTES>>>(b1, W2, b2, out, Nn);
}

// round 17
// speedup vs baseline: 1.0388x; 1.0388x over previous
#include <cuda_runtime.h>
#include <cuda_fp16.h>
#include <cstdint>
#include <math.h>

#define Hh   4
#define Cc   64
#define HC   256
#define INC  256
#define HIDD 64
#define OUTC 40
#define NEG  0.2f

#define N_MAX  50048
#define E_MAX  800000
#define ET_MAX (E_MAX + N_MAX)

// ---------------- static scratch (zero-initialized at load; self-resetting) ----------------
__device__ __align__(16) __half g_hh[(size_t)N_MAX * HC];    // h in fp16
__device__ __align__(16) __half g_agg[(size_t)N_MAX * HC];   // relu(agg/den+bias), fp16
__device__ float g_asrc[N_MAX * Hh];
__device__ float g_adst[N_MAX * Hh];
__device__ int   g_deg[N_MAX];
__device__ int   g_cnt[N_MAX];
__device__ int   g_off[N_MAX];
__device__ int   g_cursor;
__device__ int   g_csr_src[ET_MAX];
__device__ __align__(16) __half g_eeh[(size_t)ET_MAX * Hh];  // exp(logit), fp16

// fp16 operands for tensor-core GEMMs
__device__ __align__(16) __half g_xhi[(size_t)N_MAX * 256];
__device__ __align__(16) __half g_bhi[256 * 256];            // B[n,k] = W[k,n]
__device__ __align__(16) __half g_w1hi[64 * 256];            // W1[k,n] -> [n,k] hi
__device__ __align__(16) __half g_w1lo[64 * 256];            // lo

__device__ __forceinline__ int clampi(int v, int n) {
    return (v < 0) ? 0 : ((v >= n) ? n - 1 : v);
}

// ---------------- packed fp32x2 helpers ----------------
__device__ __forceinline__ unsigned long long pk2(float lo, float hi) {
    unsigned long long r;
    asm("mov.b64 %0, {%1, %2};" : "=l"(r) : "f"(lo), "f"(hi));
    return r;
}
__device__ __forceinline__ float2 upk2(unsigned long long v) {
    float lo, hi;
    asm("mov.b64 {%0, %1}, %2;" : "=f"(lo), "=f"(hi) : "l"(v));
    return make_float2(lo, hi);
}
__device__ __forceinline__ unsigned long long ffma2(unsigned long long a,
                                                    unsigned long long b,
                                                    unsigned long long c) {
    unsigned long long d;
    asm("fma.rn.f32x2 %0, %1, %2, %3;" : "=l"(d) : "l"(a), "l"(b), "l"(c));
    return d;
}

// ---------------- warp-level fp16 MMA + ldmatrix ----------------
__device__ __forceinline__ void mma_f16(float* d, const uint32_t* a, const uint32_t* b) {
    asm volatile(
        "mma.sync.aligned.m16n8k16.row.col.f32.f16.f16.f32 "
        "{%0,%1,%2,%3}, {%4,%5,%6,%7}, {%8,%9}, {%0,%1,%2,%3};"
        : "+f"(d[0]), "+f"(d[1]), "+f"(d[2]), "+f"(d[3])
        : "r"(a[0]), "r"(a[1]), "r"(a[2]), "r"(a[3]), "r"(b[0]), "r"(b[1]));
}
__device__ __forceinline__ void ldsm_x4(uint32_t* r, uint32_t addr) {
    asm volatile("ldmatrix.sync.aligned.m8n8.x4.shared.b16 {%0,%1,%2,%3}, [%4];"
                 : "=r"(r[0]), "=r"(r[1]), "=r"(r[2]), "=r"(r[3]) : "r"(addr));
}

// ---------------- cp.async helpers ----------------
__device__ __forceinline__ uint32_t smem_u32(const void* p) {
    uint32_t a;
    asm("{ .reg .u64 t; cvta.to.shared.u64 t, %1; cvt.u32.u64 %0, t; }" : "=r"(a) : "l"(p));
    return a;
}
__device__ __forceinline__ void cpa16(uint32_t dst, const void* src, bool pred) {
    int sz = pred ? 16 : 0;
    asm volatile("cp.async.cg.shared.global [%0], [%1], 16, %2;"
                 :: "r"(dst), "l"(src), "r"(sz));
}
#define CPA_COMMIT() asm volatile("cp.async.commit_group;" ::: "memory")
#define CPA_WAIT(n)  asm volatile("cp.async.wait_group %0;" :: "n"(n) : "memory")

// ---------------- fused: fp32->fp16 x  +  edge in-degree count ----------------
__global__ void convx_deg_kernel(const float* __restrict__ x,
                                 const int* __restrict__ ei,
                                 int Nn, int E, int ET) {
    int i = blockIdx.x * blockDim.x + threadIdx.x;
    int tot = Nn * 64;
    if (i < tot) {
        float4 v = ((const float4*)x)[i];
        __half2* ph = (__half2*)g_xhi;
        ph[i * 2 + 0] = __floats2half2_rn(v.x, v.y);
        ph[i * 2 + 1] = __floats2half2_rn(v.z, v.w);
    }
    if (i < ET) {
        int d = (i < E) ? clampi(ei[(size_t)E + i], Nn) : (i - E);
        atomicAdd(&g_deg[d], 1);
    }
}

// ---------------- fused: W -> bhi, W1 -> w1hi/lo, CSR offsets ----------------
__global__ void convw_off_kernel(const float* __restrict__ W,
                                 const float* __restrict__ W1, int Nn) {
    int idx = blockIdx.x * blockDim.x + threadIdx.x;
    if (idx < 256 * 256) {
        int n = idx & 255, k = idx >> 8;
        g_bhi[n * 256 + k] = __float2half_rn(W[k * 256 + n]);
    }
    if (idx < 64 * 256) {
        int n = idx & 63, k = idx >> 6;
        float w = W1[k * 64 + n];
        __half h = __float2half_rn(w);
        __half l = __float2half_rn(w - __half2float(h));
        g_w1hi[n * 256 + k] = h;
        g_w1lo[n * 256 + k] = l;
    }
    if (idx < Nn)
        g_off[idx] = atomicAdd(&g_cursor, g_deg[idx]);
}

// ---------------- tensor GEMM (1-term fp16) + fused attention epilogue ----------------
// 256 threads, 8 warps 4m x 2n (warp tile 32x64), 2 CTAs/SM for overlap.
#define APAD    72
#define TILE_EL (128 * APAD)
#define STAGE_EL (2 * TILE_EL)
#define GEMM_SMEM_BYTES (2 * STAGE_EL * 2)   // 73728

__global__ void __launch_bounds__(256, 2)
gemm_mma_kernel(const float* __restrict__ att_src,
                const float* __restrict__ att_dst, int Nn) {
    extern __shared__ __half sm[];
    int tid  = threadIdx.x;
    int wid  = tid >> 5;
    int lane = tid & 31;
    int gid  = lane >> 2;
    int tig  = lane & 3;
    int wm   = (wid & 3) * 32;
    int wn   = (wid >> 2) * 64;
    int m0 = blockIdx.x * 128;
    int n0 = blockIdx.y * 128;

    float acc[2][8][4];
#pragma unroll
    for (int mt = 0; mt < 2; mt++)
#pragma unroll
        for (int nt = 0; nt < 8; nt++)
#pragma unroll
            for (int q = 0; q < 4; q++) acc[mt][nt][q] = 0.f;

    uint32_t aoff = (uint32_t)((wm + ((lane >> 3) & 1) * 8 + (lane & 7)) * APAD
                               + (lane >> 4) * 8) * 2;
    uint32_t boff = (uint32_t)((wn + (lane >> 4) * 8 + (lane & 7)) * APAD
                               + ((lane >> 3) & 1) * 8) * 2;

    auto stage_load = [&](int st, int kk) {
        __half* base = sm + st * STAGE_EL;
        uint32_t sA = smem_u32(base);
        uint32_t sB = sA + TILE_EL * 2;
#pragma unroll
        for (int j0 = 0; j0 < 1024; j0 += 256) {
            int j = j0 + tid;
            int r = j >> 3, u = (j & 7) * 8;
            uint32_t so = (uint32_t)(r * APAD + u) * 2;
            bool am = (m0 + r) < Nn;
            size_t ga = (size_t)(m0 + r) * 256 + kk + u;
            size_t gb = (size_t)(n0 + r) * 256 + kk + u;
            cpa16(sA + so, g_xhi + ga, am);
            cpa16(sB + so, g_bhi + gb, true);
        }
        CPA_COMMIT();
    };

    stage_load(0, 0);

    for (int c = 0; c < 4; c++) {
        if (c < 3) stage_load((c + 1) & 1, (c + 1) * 64);
        if (c < 3) { CPA_WAIT(1); } else { CPA_WAIT(0); }
        __syncthreads();

        uint32_t base = smem_u32(sm + (c & 1) * STAGE_EL);
        uint32_t aHi = base + aoff;
        uint32_t bHi = base + TILE_EL * 2 + boff;

#pragma unroll
        for (int ks = 0; ks < 64; ks += 16) {
            uint32_t ahi[2][4], bhi[4][4];
#pragma unroll
            for (int mt = 0; mt < 2; mt++) {
                uint32_t d = (uint32_t)(mt * 16 * APAD + ks) * 2;
                ldsm_x4(ahi[mt], aHi + d);
            }
#pragma unroll
            for (int p = 0; p < 4; p++) {
                uint32_t d = (uint32_t)(p * 16 * APAD + ks) * 2;
                ldsm_x4(bhi[p], bHi + d);
            }
#pragma unroll
            for (int mt = 0; mt < 2; mt++)
#pragma unroll
                for (int nt = 0; nt < 8; nt++)
                    mma_f16(acc[mt][nt], ahi[mt], &bhi[nt >> 1][(nt & 1) * 2]);
        }
        __syncthreads();
    }

    // ---- epilogue 1: store h as fp16 ----
#pragma unroll
    for (int mt = 0; mt < 2; mt++) {
        int row = m0 + wm + mt * 16 + gid;
#pragma unroll
        for (int nt = 0; nt < 8; nt++) {
            int col = n0 + wn + nt * 8 + tig * 2;
            if (row < Nn)
                *(__half2*)(g_hh + (size_t)row * 256 + col) =
                    __floats2half2_rn(acc[mt][nt][0], acc[mt][nt][1]);
            if (row + 8 < Nn)
                *(__half2*)(g_hh + (size_t)(row + 8) * 256 + col) =
                    __floats2half2_rn(acc[mt][nt][2], acc[mt][nt][3]);
        }
    }

    // ---- epilogue 2: fused attention logits ----
    float* sA = (float*)sm;          // [128][2]
    float* sD = sA + 256;            // [128][2]
    if (tid < 256) { sA[tid] = 0.f; sD[tid] = 0.f; }
    __syncthreads();

    int lh = wn >> 6;                // local head 0/1 (warp-uniform)
    const float* ats = att_src + (blockIdx.y * 2 + lh) * 64;
    const float* atd = att_dst + (blockIdx.y * 2 + lh) * 64;

#pragma unroll
    for (int mt = 0; mt < 2; mt++) {
        float s0 = 0.f, d0 = 0.f, s1 = 0.f, d1 = 0.f;
#pragma unroll
        for (int nt = 0; nt < 8; nt++)
#pragma unroll
            for (int q = 0; q < 2; q++) {
                int cc = nt * 8 + tig * 2 + q;   // 0..63 within head
                float ws = __ldg(ats + cc);
                float wd = __ldg(atd + cc);
                s0 = fmaf(acc[mt][nt][q], ws, s0);
                d0 = fmaf(acc[mt][nt][q], wd, d0);
                s1 = fmaf(acc[mt][nt][q + 2], ws, s1);
                d1 = fmaf(acc[mt][nt][q + 2], wd, d1);
            }
#pragma unroll
        for (int off = 1; off <= 2; off <<= 1) {
            s0 += __shfl_xor_sync(0xffffffffu, s0, off);
            d0 += __shfl_xor_sync(0xffffffffu, d0, off);
            s1 += __shfl_xor_sync(0xffffffffu, s1, off);
            d1 += __shfl_xor_sync(0xffffffffu, d1, off);
        }
        if (tig == 0) {
            int r0 = wm + mt * 16 + gid;
            atomicAdd(&sA[r0 * 2 + lh], s0);
            atomicAdd(&sD[r0 * 2 + lh], d0);
            atomicAdd(&sA[(r0 + 8) * 2 + lh], s1);
            atomicAdd(&sD[(r0 + 8) * 2 + lh], d1);
        }
    }
    __syncthreads();
    if (tid < 256) {
        int r = tid >> 1, h2 = tid & 1;
        int grow = m0 + r;
        if (grow < Nn) {
            int gh = blockIdx.y * 2 + h2;
            g_asrc[grow * 4 + gh] = sA[r * 2 + h2];
            g_adst[grow * 4 + gh] = sD[r * 2 + h2];
        }
    }
}

// ---------------- edge pass: exp(leaky(logit)) -> CSR slots (fp16) ----------------
__global__ void edge_fill_kernel(const int* __restrict__ ei, int E, int ET, int Nn) {
    int e = blockIdx.x * blockDim.x + threadIdx.x;
    if (e >= ET) return;
    int s, d;
    if (e < E) { s = clampi(ei[e], Nn); d = clampi(ei[(size_t)E + e], Nn); }
    else       { s = d = e - E; }
    float4 as = *(const float4*)(g_asrc + (size_t)s * Hh);
    float4 ad = *(const float4*)(g_adst + (size_t)d * Hh);
    float v[4];
    v[0] = as.x + ad.x; v[1] = as.y + ad.y; v[2] = as.z + ad.z; v[3] = as.w + ad.w;
#pragma unroll
    for (int h = 0; h < 4; h++) {
        float lv = (v[h] > 0.f) ? v[h] : NEG * v[h];
        v[h] = __expf(lv);
    }
    int slot = g_off[d] + atomicAdd(&g_cnt[d], 1);
    g_csr_src[slot] = s;
    uint2 pv;
    *(__half2*)&pv.x = __floats2half2_rn(v[0], v[1]);
    *(__half2*)&pv.y = __floats2half2_rn(v[2], v[3]);
    *(uint2*)(g_eeh + (size_t)slot * Hh) = pv;
}

// ---------------- aggregation: 32 threads/node, fp16 gather/weights, fp16 out ----------------
// Also self-resets per-node counters for the next graph replay.
__global__ void agg_kernel(const float* __restrict__ bias_conv, int Nn) {
    int node = blockIdx.x * 8 + (threadIdx.x >> 5);
    int l    = threadIdx.x & 31;
    if (node >= Nn) return;
    int beg = g_off[node];
    int deg = g_deg[node];
    int hd  = l >> 3;

    float acc[8];
#pragma unroll
    for (int q = 0; q < 8; q++) acc[q] = 0.f;
    float den = 0.f;
#pragma unroll 2
    for (int i = 0; i < deg; i++) {
        int slot = beg + i;
        int s    = g_csr_src[slot];
        float a  = __half2float(g_eeh[(size_t)slot * Hh + hd]);
        uint4 hv = *(const uint4*)(g_hh + (size_t)s * 256 + l * 8);
        __half2 p0 = *(__half2*)&hv.x, p1 = *(__half2*)&hv.y;
        __half2 p2 = *(__half2*)&hv.z, p3 = *(__half2*)&hv.w;
        float2 f0 = __half22float2(p0), f1 = __half22float2(p1);
        float2 f2 = __half22float2(p2), f3 = __half22float2(p3);
        den += a;
        acc[0] = fmaf(a, f0.x, acc[0]); acc[1] = fmaf(a, f0.y, acc[1]);
        acc[2] = fmaf(a, f1.x, acc[2]); acc[3] = fmaf(a, f1.y, acc[3]);
        acc[4] = fmaf(a, f2.x, acc[4]); acc[5] = fmaf(a, f2.y, acc[5]);
        acc[6] = fmaf(a, f3.x, acc[6]); acc[7] = fmaf(a, f3.y, acc[7]);
    }
    float r = 1.f / den;
    float4 b0 = *(const float4*)(bias_conv + l * 8);
    float4 b1 = *(const float4*)(bias_conv + l * 8 + 4);
    float o[8];
    o[0] = fmaxf(fmaf(acc[0], r, b0.x), 0.f);
    o[1] = fmaxf(fmaf(acc[1], r, b0.y), 0.f);
    o[2] = fmaxf(fmaf(acc[2], r, b0.z), 0.f);
    o[3] = fmaxf(fmaf(acc[3], r, b0.w), 0.f);
    o[4] = fmaxf(fmaf(acc[4], r, b1.x), 0.f);
    o[5] = fmaxf(fmaf(acc[5], r, b1.y), 0.f);
    o[6] = fmaxf(fmaf(acc[6], r, b1.z), 0.f);
    o[7] = fmaxf(fmaf(acc[7], r, b1.w), 0.f);
    uint4 ov;
    ((__half2*)&ov)[0] = __floats2half2_rn(o[0], o[1]);
    ((__half2*)&ov)[1] = __floats2half2_rn(o[2], o[3]);
    ((__half2*)&ov)[2] = __floats2half2_rn(o[4], o[5]);
    ((__half2*)&ov)[3] = __floats2half2_rn(o[6], o[7]);
    *(uint4*)(g_agg + (size_t)node * HC + l * 8) = ov;

    // self-reset for next replay (each node visited exactly once)
    if (l == 0) {
        g_deg[node] = 0;
        g_cnt[node] = 0;
        if (node == 0) g_cursor = 0;
    }
}

// ---------------- fused MLP via tensor cores (2 CTAs/SM) ----------------
#define MTILE_A   (128 * APAD)
#define MTILE_B   (64 * APAD)
#define MSTAGE_EL (MTILE_A + 2 * MTILE_B)
#define MLP_SMEM_BYTES (2 * MSTAGE_EL * 2)   // 73728

__global__ void __launch_bounds__(256, 2)
mlp_mma_kernel(const float* __restrict__ b1,
               const float* __restrict__ W2, const float* __restrict__ b2,
               float* __restrict__ out, int M) {
    extern __shared__ __half sm[];
    int tid  = threadIdx.x;
    int wid  = tid >> 5;
    int lane = tid & 31;
    int gid  = lane >> 2;
    int tig  = lane & 3;
    int wm   = (wid & 3) * 32;
    int wn   = (wid >> 2) * 32;
    int m0 = blockIdx.x * 128;

    float acc[2][4][4];
#pragma unroll
    for (int mt = 0; mt < 2; mt++)
#pragma unroll
        for (int nt = 0; nt < 4; nt++)
#pragma unroll
            for (int q = 0; q < 4; q++) acc[mt][nt][q] = 0.f;

    uint32_t aoff = (uint32_t)((wm + ((lane >> 3) & 1) * 8 + (lane & 7)) * APAD
                               + (lane >> 4) * 8) * 2;
    uint32_t boff = (uint32_t)((wn + (lane >> 4) * 8 + (lane & 7)) * APAD
                               + ((lane >> 3) & 1) * 8) * 2;

    auto stage_load = [&](int st, int kk) {
        __half* base = sm + st * MSTAGE_EL;
        uint32_t sA  = smem_u32(base);
        uint32_t sBh = sA + MTILE_A * 2;
        uint32_t sBl = sBh + MTILE_B * 2;
#pragma unroll
        for (int j0 = 0; j0 < 1024; j0 += 256) {
            int j = j0 + tid;
            int r = j >> 3, u = (j & 7) * 8;
            uint32_t so = (uint32_t)(r * APAD + u) * 2;
            bool am = (m0 + r) < M;
            cpa16(sA + so, g_agg + (size_t)(m0 + r) * 256 + kk + u, am);
        }
#pragma unroll
        for (int j0 = 0; j0 < 512; j0 += 256) {
            int j = j0 + tid;
            int r = j >> 3, u = (j & 7) * 8;
            uint32_t so = (uint32_t)(r * APAD + u) * 2;
            cpa16(sBh + so, g_w1hi + (size_t)r * 256 + kk + u, true);
            cpa16(sBl + so, g_w1lo + (size_t)r * 256 + kk + u, true);
        }
        CPA_COMMIT();
    };

    stage_load(0, 0);

    for (int c = 0; c < 4; c++) {
        if (c < 3) stage_load((c + 1) & 1, (c + 1) * 64);
        if (c < 3) { CPA_WAIT(1); } else { CPA_WAIT(0); }
        __syncthreads();

        uint32_t base = smem_u32(sm + (c & 1) * MSTAGE_EL);
        uint32_t aA  = base + aoff;
        uint32_t bHi = base + MTILE_A * 2 + boff;
        uint32_t bLo = bHi + MTILE_B * 2;

#pragma unroll
        for (int ks = 0; ks < 64; ks += 16) {
            uint32_t av[2][4], bh[2][4], bl[2][4];
#pragma unroll
            for (int mt = 0; mt < 2; mt++) {
                uint32_t d = (uint32_t)(mt * 16 * APAD + ks) * 2;
                ldsm_x4(av[mt], aA + d);
            }
#pragma unroll
            for (int p = 0; p < 2; p++) {
                uint32_t d = (uint32_t)(p * 16 * APAD + ks) * 2;
                ldsm_x4(bh[p], bHi + d);
                ldsm_x4(bl[p], bLo + d);
            }
#pragma unroll
            for (int mt = 0; mt < 2; mt++)
#pragma unroll
                for (int nt = 0; nt < 4; nt++)
                    mma_f16(acc[mt][nt], av[mt], &bh[nt >> 1][(nt & 1) * 2]);
#pragma unroll
            for (int mt = 0; mt < 2; mt++)
#pragma unroll
                for (int nt = 0; nt < 4; nt++)
                    mma_f16(acc[mt][nt], av[mt], &bl[nt >> 1][(nt & 1) * 2]);
        }
        __syncthreads();
    }

    // ---- epilogue: bias+relu -> sHid (smem fp16), then per-thread mlp2 ----
    __half* sHid = sm;                          // [128][66]
    float*  sW2  = (float*)(sm + 8448);         // [64][40]
    float*  sb2  = sW2 + 2560;                  // [40]

    for (int i = tid; i < 2560; i += 256) sW2[i] = W2[i];
    if (tid < 40) sb2[tid] = b2[tid];

#pragma unroll
    for (int mt = 0; mt < 2; mt++) {
        int rl = wm + mt * 16 + gid;
#pragma unroll
        for (int nt = 0; nt < 4; nt++) {
            int col = wn + nt * 8 + tig * 2;
            float bc0 = __ldg(b1 + col), bc1 = __ldg(b1 + col + 1);
            *(__half2*)(sHid + rl * 66 + col) =
                __floats2half2_rn(fmaxf(acc[mt][nt][0] + bc0, 0.f),
                                  fmaxf(acc[mt][nt][1] + bc1, 0.f));
            *(__half2*)(sHid + (rl + 8) * 66 + col) =
                __floats2half2_rn(fmaxf(acc[mt][nt][2] + bc0, 0.f),
                                  fmaxf(acc[mt][nt][3] + bc1, 0.f));
        }
    }
    __syncthreads();

    int row  = tid & 127;
    int half_ = tid >> 7;          // 0/1: which 20 output cols
    int node = m0 + row;
    if (node >= M) return;

    unsigned long long acc2[10];
#pragma unroll
    for (int j = 0; j < 10; j++) {
        float2 bv = *(const float2*)(sb2 + half_ * 20 + j * 2);
        acc2[j] = pk2(bv.x, bv.y);
    }
#pragma unroll 4
    for (int k = 0; k < HIDD; k++) {
        float xv = __half2float(sHid[row * 66 + k]);
        unsigned long long xp = pk2(xv, xv);
        const float2* wrow = (const float2*)(sW2 + k * OUTC + half_ * 20);
#pragma unroll
        for (int j = 0; j < 10; j++) {
            float2 w = wrow[j];
            acc2[j] = ffma2(xp, pk2(w.x, w.y), acc2[j]);
        }
    }
    float* orow = out + (size_t)node * OUTC + half_ * 20;
#pragma unroll
    for (int j = 0; j < 10; j++) {
        float2 v = upk2(acc2[j]);
        *(float2*)(orow + j * 2) = v;
    }
}

// ---------------- launch ----------------
extern "C" void kernel_launch(void* const* d_in, const int* in_sizes, int n_in,
                              void* d_out, int out_size) {
    const float* x         = (const float*)d_in[0];
    const int*   ei        = (const int*)d_in[1];      // int32
    const float* W         = (const float*)d_in[2];
    const float* att_src   = (const float*)d_in[3];
    const float* att_dst   = (const float*)d_in[4];
    const float* bias_conv = (const float*)d_in[5];
    const float* W1        = (const float*)d_in[6];
    const float* b1        = (const float*)d_in[7];
    const float* W2        = (const float*)d_in[8];
    const float* b2        = (const float*)d_in[9];
    float*       out       = (float*)d_out;

    int Nn = in_sizes[0] / INC;
    int E  = in_sizes[1] / 2;
    int ET = E + Nn;

    cudaFuncSetAttribute(gemm_mma_kernel,
                         cudaFuncAttributeMaxDynamicSharedMemorySize, GEMM_SMEM_BYTES);
    cudaFuncSetAttribute(mlp_mma_kernel,
                         cudaFuncAttributeMaxDynamicSharedMemorySize, MLP_SMEM_BYTES);

    int t1 = Nn * 64; if (ET > t1) t1 = ET;
    convx_deg_kernel<<<(t1 + 255) / 256, 256>>>(x, ei, Nn, E, ET);
    convw_off_kernel<<<(256 * 256 + 255) / 256, 256>>>(W, W1, Nn);

    dim3 gt((Nn + 127) / 128, 2);
    gemm_mma_kernel<<<gt, 256, GEMM_SMEM_BYTES>>>(att_src, att_dst, Nn);

    edge_fill_kernel<<<(ET + 255) / 256, 256>>>(ei, E, ET, Nn);

    agg_kernel<<<(Nn + 7) / 8, 256>>>(bias_conv, Nn);

    mlp_mma_kernel<<<(Nn + 127) / 128, 256, MLP_SMEM_BYTES>>>(b1, W2, b2, out, Nn);
}